// round 1
// baseline (speedup 1.0000x reference)
#include <cuda_runtime.h>
#include <cuda_bf16.h>

// ---------------------------------------------------------------------------
// MoonElecOut: fused electron-update block.
//   elec1 = silu(elec@W_in + b_in)
//   pair filter -> gamma[n,k,:], hinit_msg[n,d] = sum_k silu(elec1+hinit_nb)*gamma
//   t1 = silu(elec1@W1 + b1 + hinit_msg)
//   t2 = silu(t1@W2 + b2 + msg)
//   out = (silu(t2@W3 + b3) + elec1) * scale
// ---------------------------------------------------------------------------

constexpr int N_ELEC = 8192;
constexpr int DIM    = 256;
constexpr int NNB    = 24;
constexpr int F0     = 32;
constexpr int F1     = 16;
constexpr int NENV   = 8;
constexpr float CUTOFF = 5.0f;

// scratch (device-global; no allocation inside kernel_launch)
__device__ float g_elec1[N_ELEC * DIM];
__device__ float g_hmsg [N_ELEC * DIM];
__device__ float g_t1   [N_ELEC * DIM];
__device__ float g_t2   [N_ELEC * DIM];

__device__ __forceinline__ float silu_f(float x) {
    return x / (1.0f + __expf(-x));
}

// ---------------------------------------------------------------------------
// GEMM: out[M=8192, N=256] = epilogue(A[8192,256] @ W[256,256])
// BM=128, BN=64, BK=16. 256 threads, each 8x4 outputs.
// MODE 0: out = silu(acc + bias)
// MODE 1: out = silu(acc + bias + extra)
// MODE 2: out = (silu(acc + bias) + res) * (*scale_p)
// ---------------------------------------------------------------------------
template <int MODE>
__global__ __launch_bounds__(256) void gemm_silu(
    const float* __restrict__ A, const float* __restrict__ W,
    const float* __restrict__ bias, const float* __restrict__ extra,
    const float* __restrict__ res, const float* __restrict__ scale_p,
    float* __restrict__ out)
{
    __shared__ float As[16][128];
    __shared__ float Bs[16][64];

    const int tid = threadIdx.x;
    const int bm  = blockIdx.y;   // 64 tiles of 128 rows
    const int bn  = blockIdx.x;   // 4 tiles of 64 cols

    const int tx = tid & 15;      // 16 col-groups of 4
    const int ty = tid >> 4;      // 16 row-groups of 8

    // A load mapping: each thread loads 8 consecutive k of one row
    const int arow = tid >> 1;          // 0..127
    const int acol = (tid & 1) * 8;     // 0 or 8
    // B load mapping: one float4 per thread
    const int brow = tid >> 4;          // 0..15
    const int bcol = (tid & 15) * 4;    // 0..60

    const float* Ag = A + (size_t)(bm * 128 + arow) * DIM + acol;
    const float* Wg = W + (size_t)brow * DIM + bn * 64 + bcol;

    float acc[8][4];
#pragma unroll
    for (int i = 0; i < 8; i++)
#pragma unroll
        for (int j = 0; j < 4; j++) acc[i][j] = 0.0f;

    for (int k0 = 0; k0 < DIM; k0 += 16) {
        float4 a0 = *(const float4*)(Ag + k0);
        float4 a1 = *(const float4*)(Ag + k0 + 4);
        float4 b0 = *(const float4*)(Wg + (size_t)k0 * DIM);

        As[acol + 0][arow] = a0.x; As[acol + 1][arow] = a0.y;
        As[acol + 2][arow] = a0.z; As[acol + 3][arow] = a0.w;
        As[acol + 4][arow] = a1.x; As[acol + 5][arow] = a1.y;
        As[acol + 6][arow] = a1.z; As[acol + 7][arow] = a1.w;
        *(float4*)&Bs[brow][bcol] = b0;
        __syncthreads();

#pragma unroll
        for (int kk = 0; kk < 16; kk++) {
            float af[8], bfr[4];
            *(float4*)(af)     = *(const float4*)&As[kk][ty * 8];
            *(float4*)(af + 4) = *(const float4*)&As[kk][ty * 8 + 4];
            *(float4*)(bfr)    = *(const float4*)&Bs[kk][tx * 4];
#pragma unroll
            for (int i = 0; i < 8; i++)
#pragma unroll
                for (int j = 0; j < 4; j++)
                    acc[i][j] += af[i] * bfr[j];
        }
        __syncthreads();
    }

    // epilogue
    const int col0 = bn * 64 + tx * 4;
    float sc = 1.0f;
    if (MODE == 2) sc = *scale_p;
    float4 bv = *(const float4*)(bias + col0);

#pragma unroll
    for (int i = 0; i < 8; i++) {
        const int row = bm * 128 + ty * 8 + i;
        const size_t off = (size_t)row * DIM + col0;
        float v[4] = { acc[i][0] + bv.x, acc[i][1] + bv.y,
                       acc[i][2] + bv.z, acc[i][3] + bv.w };
        if (MODE == 1) {
            float4 e = *(const float4*)(extra + off);
            v[0] += e.x; v[1] += e.y; v[2] += e.z; v[3] += e.w;
        }
        float4 o;
        o.x = silu_f(v[0]); o.y = silu_f(v[1]);
        o.z = silu_f(v[2]); o.w = silu_f(v[3]);
        if (MODE == 2) {
            float4 rr = *(const float4*)(res + off);
            o.x = (o.x + rr.x) * sc; o.y = (o.y + rr.y) * sc;
            o.z = (o.z + rr.z) * sc; o.w = (o.w + rr.w) * sc;
        }
        *(float4*)(out + off) = o;
    }
}

// ---------------------------------------------------------------------------
// Pair kernel: 8 electrons per block, 256 threads.
// Phase 1: threads 0..191 compute beta[16] for one (n,k) pair.
// Phase 2: thread d holds Wsame[:,d]/Wdiff[:,d] in regs, reduces over k.
// ---------------------------------------------------------------------------
constexpr int NPB = 8;               // electrons per block
constexpr int PAIRS = NPB * NNB;     // 192

__global__ __launch_bounds__(256) void pair_kernel(
    const float* __restrict__ elec1,
    const float* __restrict__ r,
    const float* __restrict__ r_nb,
    const int*   __restrict__ s,
    const int*   __restrict__ s_nb,
    const float* __restrict__ hinit_nb,
    const float* __restrict__ ee_scales,
    const float* __restrict__ ee_kernel,
    const float* __restrict__ ee_bias,
    const float* __restrict__ Wf,
    const float* __restrict__ bf,
    const float* __restrict__ Wsame,
    const float* __restrict__ Wdiff,
    float* __restrict__ hinit_msg)
{
    __shared__ float beta_s[PAIRS][F1];          // 12 KB
    __shared__ float eek_s[4 * F0];              // 128
    __shared__ float eeb_s[F0];                  // 32
    __shared__ float wf_s[(F0 + NENV) * F1];     // 640
    __shared__ float bfv_s[F1];                  // 16
    __shared__ float scl_s[NENV];                // 8
    __shared__ unsigned char mask_s[PAIRS];

    const int tid = threadIdx.x;
    const int n0  = blockIdx.x * NPB;

    // stage small params
    for (int i = tid; i < 4 * F0; i += 256) eek_s[i] = ee_kernel[i];
    for (int i = tid; i < F0; i += 256)     eeb_s[i] = ee_bias[i];
    for (int i = tid; i < (F0 + NENV) * F1; i += 256) wf_s[i] = Wf[i];
    if (tid < F1)   bfv_s[tid] = bf[tid];
    if (tid < NENV) scl_s[tid] = ee_scales[tid];
    __syncthreads();

    // ---- Phase 1: per-pair beta ----
    if (tid < PAIRS) {
        const int nl = tid / NNB;
        const int k  = tid % NNB;
        const int n  = n0 + nl;

        const float rx = r[n * 3 + 0];
        const float ry = r[n * 3 + 1];
        const float rz = r[n * 3 + 2];
        const float* rn = r_nb + (size_t)(n * NNB + k) * 3;
        const float dx = rn[0] - rx;
        const float dy = rn[1] - ry;
        const float dz = rn[2] - rz;
        const float dist = sqrtf(dx * dx + dy * dy + dz * dz + 1e-12f);

        float feats[4] = { dist, dx, dy, dz };
        float h[F0];
#pragma unroll
        for (int j = 0; j < F0; j++) {
            float t = eeb_s[j];
#pragma unroll
            for (int f = 0; f < 4; f++) t += feats[f] * eek_s[f * F0 + j];
            h[j] = silu_f(t);
        }
        float env[NENV];
#pragma unroll
        for (int e = 0; e < NENV; e++) {
            float q = dist / scl_s[e];
            env[e] = __expf(-q * q);
        }
        const float xx  = dist * (1.0f / CUTOFF);
        const float cut = (dist < CUTOFF)
                        ? (1.0f - xx) * (1.0f - xx) * (1.0f + 2.0f * xx)
                        : 0.0f;
#pragma unroll
        for (int i = 0; i < F1; i++) {
            float b = bfv_s[i];
#pragma unroll
            for (int j = 0; j < F0; j++)   b += h[j]   * wf_s[j * F1 + i];
#pragma unroll
            for (int e = 0; e < NENV; e++) b += env[e] * wf_s[(F0 + e) * F1 + i];
            beta_s[tid][i] = b * cut;
        }
        mask_s[tid] = (s[n] == s_nb[n * NNB + k]) ? 1 : 0;
    }
    __syncthreads();

    // ---- Phase 2: per-channel reduction over neighbors ----
    const int d = tid;  // 0..255
    float wsame[F1], wdiff[F1];
#pragma unroll
    for (int i = 0; i < F1; i++) {
        wsame[i] = Wsame[i * DIM + d];
        wdiff[i] = Wdiff[i * DIM + d];
    }

    for (int nl = 0; nl < NPB; nl++) {
        const int n = n0 + nl;
        const float e1 = elec1[(size_t)n * DIM + d];
        const float* hb = hinit_nb + ((size_t)n * NNB) * DIM + d;
        float acc = 0.0f;
#pragma unroll
        for (int k = 0; k < NNB; k++) {
            const int pair = nl * NNB + k;
            float b[F1];
            *(float4*)(b)      = *(const float4*)&beta_s[pair][0];
            *(float4*)(b + 4)  = *(const float4*)&beta_s[pair][4];
            *(float4*)(b + 8)  = *(const float4*)&beta_s[pair][8];
            *(float4*)(b + 12) = *(const float4*)&beta_s[pair][12];
            float g = 0.0f;
            if (mask_s[pair]) {              // uniform across block
#pragma unroll
                for (int i = 0; i < F1; i++) g += b[i] * wsame[i];
            } else {
#pragma unroll
                for (int i = 0; i < F1; i++) g += b[i] * wdiff[i];
            }
            const float hv = e1 + hb[(size_t)k * DIM];
            acc += silu_f(hv) * g;
        }
        hinit_msg[(size_t)n * DIM + d] = acc;
    }
}

// ---------------------------------------------------------------------------
// launch
// ---------------------------------------------------------------------------
extern "C" void kernel_launch(void* const* d_in, const int* in_sizes, int n_in,
                              void* d_out, int out_size)
{
    const float* elec     = (const float*)d_in[0];
    const float* msg      = (const float*)d_in[1];
    const float* r        = (const float*)d_in[2];
    const float* r_nb     = (const float*)d_in[3];
    const int*   s        = (const int*)  d_in[4];
    const int*   s_nb     = (const int*)  d_in[5];
    const float* hinit_nb = (const float*)d_in[6];
    const float* W_in     = (const float*)d_in[7];
    const float* b_in     = (const float*)d_in[8];
    const float* ee_scales= (const float*)d_in[9];
    const float* ee_kernel= (const float*)d_in[10];
    const float* ee_bias  = (const float*)d_in[11];
    const float* Wf       = (const float*)d_in[12];
    const float* bf       = (const float*)d_in[13];
    const float* Wsame    = (const float*)d_in[14];
    const float* Wdiff    = (const float*)d_in[15];
    const float* W1       = (const float*)d_in[16];
    const float* b1       = (const float*)d_in[17];
    const float* W2       = (const float*)d_in[18];
    const float* b2       = (const float*)d_in[19];
    const float* W3       = (const float*)d_in[20];
    const float* b3       = (const float*)d_in[21];
    const float* scale    = (const float*)d_in[22];

    float* out = (float*)d_out;

    float* elec1 = nullptr; float* hmsg = nullptr; float* t1 = nullptr; float* t2 = nullptr;
    cudaGetSymbolAddress((void**)&elec1, g_elec1);
    cudaGetSymbolAddress((void**)&hmsg,  g_hmsg);
    cudaGetSymbolAddress((void**)&t1,    g_t1);
    cudaGetSymbolAddress((void**)&t2,    g_t2);

    dim3 ggrid(DIM / 64, N_ELEC / 128);   // (4, 64)
    dim3 gblk(256);

    // elec1 = silu(elec @ W_in + b_in)
    gemm_silu<0><<<ggrid, gblk>>>(elec, W_in, b_in, nullptr, nullptr, nullptr, elec1);

    // hinit_msg
    pair_kernel<<<N_ELEC / NPB, 256>>>(elec1, r, r_nb, s, s_nb, hinit_nb,
                                       ee_scales, ee_kernel, ee_bias, Wf, bf,
                                       Wsame, Wdiff, hmsg);

    // t1 = silu(elec1 @ W1 + b1 + hinit_msg)
    gemm_silu<1><<<ggrid, gblk>>>(elec1, W1, b1, hmsg, nullptr, nullptr, t1);
    // t2 = silu(t1 @ W2 + b2 + msg)
    gemm_silu<1><<<ggrid, gblk>>>(t1, W2, b2, msg, nullptr, nullptr, t2);
    // out = (silu(t2 @ W3 + b3) + elec1) * scale
    gemm_silu<2><<<ggrid, gblk>>>(t2, W3, b3, nullptr, elec1, scale, out);
}

// round 2
// speedup vs baseline: 1.0810x; 1.0810x over previous
#include <cuda_runtime.h>
#include <cuda_bf16.h>

constexpr int N_ELEC = 8192;
constexpr int DIM    = 256;
constexpr int NNB    = 24;
constexpr int F0     = 32;
constexpr int F1     = 16;
constexpr int NENV   = 8;
constexpr float CUTOFF = 5.0f;

__device__ float g_elec1[N_ELEC * DIM];
__device__ float g_hmsg [N_ELEC * DIM];
__device__ float g_t1   [N_ELEC * DIM];
__device__ float g_t2   [N_ELEC * DIM];

typedef unsigned long long u64;

__device__ __forceinline__ u64 pk2(float x, float y) {
    u64 r; asm("mov.b64 %0, {%1,%2};" : "=l"(r) : "f"(x), "f"(y)); return r;
}
__device__ __forceinline__ float2 upk2(u64 v) {
    float2 f; asm("mov.b64 {%0,%1}, %2;" : "=f"(f.x), "=f"(f.y) : "l"(v)); return f;
}
__device__ __forceinline__ u64 f2fma(u64 a, u64 b, u64 c) {
    u64 d; asm("fma.rn.f32x2 %0, %1, %2, %3;" : "=l"(d) : "l"(a), "l"(b), "l"(c));
    return d;
}

__device__ __forceinline__ float silu_f(float x) {
    float e = __expf(-x);
    return __fdividef(x, 1.0f + e);
}

// ---------------------------------------------------------------------------
// GEMM: out[8192,256] = epilogue(A[8192,256] @ W[256,256])
// BM=64, BN=64, BK=16, 128 threads, thread tile 8x4, f32x2 packed FMA.
// MODE 0: silu(acc+bias)   MODE 1: silu(acc+bias+extra)
// MODE 2: (silu(acc+bias)+res)*scale
// ---------------------------------------------------------------------------
template <int MODE>
__global__ __launch_bounds__(128) void gemm_silu(
    const float* __restrict__ A, const float* __restrict__ W,
    const float* __restrict__ bias, const float* __restrict__ extra,
    const float* __restrict__ res, const float* __restrict__ scale_p,
    float* __restrict__ out)
{
    __shared__ __align__(16) float As[16][64];    // [k][m]
    __shared__ __align__(16) float Bs[16][128];   // [k][n duplicated]

    const int tid = threadIdx.x;
    const int bm  = blockIdx.y;   // 128 tiles of 64 rows
    const int bn  = blockIdx.x;   // 4 tiles of 64 cols

    const int tx = tid & 15;      // 16 col-groups of 4
    const int ty = tid >> 4;      // 8 row-groups of 8

    // A load: 2 threads per row, 8 floats each
    const int arow = tid >> 1;
    const int acol = (tid & 1) * 8;
    // B load: each thread 8 floats of one k-row
    const int brow = tid >> 3;          // 0..15
    const int bcol = (tid & 7) * 8;     // 0..56

    const float* Ag = A + (size_t)(bm * 64 + arow) * DIM + acol;
    const float* Wg = W + (size_t)brow * DIM + bn * 64 + bcol;

    u64 acc[4][4];
#pragma unroll
    for (int i = 0; i < 4; i++)
#pragma unroll
        for (int j = 0; j < 4; j++) acc[i][j] = 0ull;

    for (int k0 = 0; k0 < DIM; k0 += 16) {
        float4 a0 = *(const float4*)(Ag + k0);
        float4 a1 = *(const float4*)(Ag + k0 + 4);
        float4 b0 = *(const float4*)(Wg + (size_t)k0 * DIM);
        float4 b1 = *(const float4*)(Wg + (size_t)k0 * DIM + 4);

        As[acol + 0][arow] = a0.x; As[acol + 1][arow] = a0.y;
        As[acol + 2][arow] = a0.z; As[acol + 3][arow] = a0.w;
        As[acol + 4][arow] = a1.x; As[acol + 5][arow] = a1.y;
        As[acol + 6][arow] = a1.z; As[acol + 7][arow] = a1.w;
        // duplicated B: (x,x,y,y),(z,z,w,w) per float4
        *(float4*)&Bs[brow][bcol * 2 + 0]  = make_float4(b0.x, b0.x, b0.y, b0.y);
        *(float4*)&Bs[brow][bcol * 2 + 4]  = make_float4(b0.z, b0.z, b0.w, b0.w);
        *(float4*)&Bs[brow][bcol * 2 + 8]  = make_float4(b1.x, b1.x, b1.y, b1.y);
        *(float4*)&Bs[brow][bcol * 2 + 12] = make_float4(b1.z, b1.z, b1.w, b1.w);
        __syncthreads();

#pragma unroll
        for (int kk = 0; kk < 16; kk++) {
            const ulonglong2* ap = (const ulonglong2*)&As[kk][ty * 8];
            const ulonglong2* bp = (const ulonglong2*)&Bs[kk][tx * 8];
            ulonglong2 av0 = ap[0], av1 = ap[1];
            ulonglong2 bv0 = bp[0], bv1 = bp[1];
            u64 a2[4] = { av0.x, av0.y, av1.x, av1.y };
            u64 b2[4] = { bv0.x, bv0.y, bv1.x, bv1.y };
#pragma unroll
            for (int i = 0; i < 4; i++)
#pragma unroll
                for (int j = 0; j < 4; j++)
                    acc[i][j] = f2fma(a2[i], b2[j], acc[i][j]);
        }
        __syncthreads();
    }

    // unpack accumulators: row pairs
    float v[8][4];
#pragma unroll
    for (int i = 0; i < 4; i++)
#pragma unroll
        for (int j = 0; j < 4; j++) {
            float2 t = upk2(acc[i][j]);
            v[2 * i + 0][j] = t.x;
            v[2 * i + 1][j] = t.y;
        }

    const int col0 = bn * 64 + tx * 4;
    float sc = 1.0f;
    if (MODE == 2) sc = *scale_p;
    float4 bv = *(const float4*)(bias + col0);

#pragma unroll
    for (int rr = 0; rr < 8; rr++) {
        const int row = bm * 64 + ty * 8 + rr;
        const size_t off = (size_t)row * DIM + col0;
        float w0 = v[rr][0] + bv.x, w1 = v[rr][1] + bv.y;
        float w2 = v[rr][2] + bv.z, w3 = v[rr][3] + bv.w;
        if (MODE == 1) {
            float4 e = *(const float4*)(extra + off);
            w0 += e.x; w1 += e.y; w2 += e.z; w3 += e.w;
        }
        float4 o;
        o.x = silu_f(w0); o.y = silu_f(w1);
        o.z = silu_f(w2); o.w = silu_f(w3);
        if (MODE == 2) {
            float4 rv = *(const float4*)(res + off);
            o.x = (o.x + rv.x) * sc; o.y = (o.y + rv.y) * sc;
            o.z = (o.z + rv.z) * sc; o.w = (o.w + rv.w) * sc;
        }
        *(float4*)(out + off) = o;
    }
}

// ---------------------------------------------------------------------------
// Pair kernel: 8 electrons per block, 256 threads, branch-free dual-accum.
//  hinit_msg[n,d] = wd_d . (sum_k u_k beta_k) + (ws-wd)_d . (sum_k m_k u_k beta_k)
// ---------------------------------------------------------------------------
constexpr int NPB   = 8;
constexpr int PAIRS = NPB * NNB;   // 192

__global__ __launch_bounds__(256) void pair_kernel(
    const float* __restrict__ elec1,
    const float* __restrict__ r,
    const float* __restrict__ r_nb,
    const int*   __restrict__ s,
    const int*   __restrict__ s_nb,
    const float* __restrict__ hinit_nb,
    const float* __restrict__ ee_scales,
    const float* __restrict__ ee_kernel,
    const float* __restrict__ ee_bias,
    const float* __restrict__ Wf,
    const float* __restrict__ bf,
    const float* __restrict__ Wsame,
    const float* __restrict__ Wdiff,
    float* __restrict__ hinit_msg)
{
    __shared__ __align__(16) float beta_s[PAIRS][F1];   // 12 KB
    __shared__ float maskf_s[PAIRS];
    __shared__ float eek_s[4 * F0];
    __shared__ float eeb_s[F0];
    __shared__ float wf_s[(F0 + NENV) * F1];
    __shared__ float bfv_s[F1];
    __shared__ float scl_s[NENV];

    const int tid = threadIdx.x;
    const int n0  = blockIdx.x * NPB;

    for (int i = tid; i < 4 * F0; i += 256) eek_s[i] = ee_kernel[i];
    for (int i = tid; i < F0; i += 256)     eeb_s[i] = ee_bias[i];
    for (int i = tid; i < (F0 + NENV) * F1; i += 256) wf_s[i] = Wf[i];
    if (tid < F1)   bfv_s[tid] = bf[tid];
    if (tid < NENV) scl_s[tid] = ee_scales[tid];
    __syncthreads();

    // ---- Phase 1: per-pair beta (threads 0..191) ----
    if (tid < PAIRS) {
        const int nl = tid / NNB;
        const int k  = tid % NNB;
        const int n  = n0 + nl;

        const float rx = r[n * 3 + 0];
        const float ry = r[n * 3 + 1];
        const float rz = r[n * 3 + 2];
        const float* rn = r_nb + (size_t)(n * NNB + k) * 3;
        const float dx = rn[0] - rx;
        const float dy = rn[1] - ry;
        const float dz = rn[2] - rz;
        const float dist = sqrtf(dx * dx + dy * dy + dz * dz + 1e-12f);

        float feats[4] = { dist, dx, dy, dz };
        float h[F0];
#pragma unroll
        for (int j = 0; j < F0; j++) {
            float t = eeb_s[j];
#pragma unroll
            for (int f = 0; f < 4; f++) t += feats[f] * eek_s[f * F0 + j];
            h[j] = silu_f(t);
        }
        float env[NENV];
#pragma unroll
        for (int e = 0; e < NENV; e++) {
            float q = __fdividef(dist, scl_s[e]);
            env[e] = __expf(-q * q);
        }
        const float xx  = dist * (1.0f / CUTOFF);
        const float cut = (dist < CUTOFF)
                        ? (1.0f - xx) * (1.0f - xx) * (1.0f + 2.0f * xx)
                        : 0.0f;
#pragma unroll
        for (int i = 0; i < F1; i++) {
            float b = bfv_s[i];
#pragma unroll
            for (int j = 0; j < F0; j++)   b += h[j]   * wf_s[j * F1 + i];
#pragma unroll
            for (int e = 0; e < NENV; e++) b += env[e] * wf_s[(F0 + e) * F1 + i];
            beta_s[tid][i] = b * cut;
        }
        maskf_s[tid] = (s[n] == s_nb[n * NNB + k]) ? 1.0f : 0.0f;
    }
    __syncthreads();

    // ---- Phase 2: per-channel reduction (thread d = 0..255) ----
    const int d = tid;
    u64 wd2[8], wsd2[8];
#pragma unroll
    for (int i = 0; i < 8; i++) {
        float d0 = Wdiff[(2 * i + 0) * DIM + d];
        float d1 = Wdiff[(2 * i + 1) * DIM + d];
        float s0 = Wsame[(2 * i + 0) * DIM + d] - d0;
        float s1 = Wsame[(2 * i + 1) * DIM + d] - d1;
        wd2[i]  = pk2(d0, d1);
        wsd2[i] = pk2(s0, s1);
    }

    for (int nl = 0; nl < NPB; nl++) {
        const int n = n0 + nl;
        const float e1 = elec1[(size_t)n * DIM + d];
        const float* hb = hinit_nb + ((size_t)n * NNB) * DIM + d;

        u64 vall[8], vsm[8];
#pragma unroll
        for (int i = 0; i < 8; i++) { vall[i] = 0ull; vsm[i] = 0ull; }

#pragma unroll
        for (int h = 0; h < 2; h++) {
            float uu[12];
#pragma unroll
            for (int kk = 0; kk < 12; kk++) {
                const int k = h * 12 + kk;
                uu[kk] = silu_f(e1 + hb[(size_t)k * DIM]);
            }
#pragma unroll
            for (int kk = 0; kk < 12; kk++) {
                const int k = h * 12 + kk;
                const int pair = nl * NNB + k;
                const float m  = maskf_s[pair];
                const float um = uu[kk] * m;
                const u64 u2   = pk2(uu[kk], uu[kk]);
                const u64 um2  = pk2(um, um);
                const u64* bp  = (const u64*)beta_s[pair];
#pragma unroll
                for (int i = 0; i < 8; i++) {
                    const u64 b = bp[i];
                    vall[i] = f2fma(u2,  b, vall[i]);
                    vsm[i]  = f2fma(um2, b, vsm[i]);
                }
            }
        }

        u64 r2 = 0ull;
#pragma unroll
        for (int i = 0; i < 8; i++) r2 = f2fma(vall[i], wd2[i], r2);
#pragma unroll
        for (int i = 0; i < 8; i++) r2 = f2fma(vsm[i], wsd2[i], r2);
        float2 rr = upk2(r2);
        hinit_msg[(size_t)n * DIM + d] = rr.x + rr.y;
    }
}

// ---------------------------------------------------------------------------
extern "C" void kernel_launch(void* const* d_in, const int* in_sizes, int n_in,
                              void* d_out, int out_size)
{
    const float* elec     = (const float*)d_in[0];
    const float* msg      = (const float*)d_in[1];
    const float* r        = (const float*)d_in[2];
    const float* r_nb     = (const float*)d_in[3];
    const int*   s        = (const int*)  d_in[4];
    const int*   s_nb     = (const int*)  d_in[5];
    const float* hinit_nb = (const float*)d_in[6];
    const float* W_in     = (const float*)d_in[7];
    const float* b_in     = (const float*)d_in[8];
    const float* ee_scales= (const float*)d_in[9];
    const float* ee_kernel= (const float*)d_in[10];
    const float* ee_bias  = (const float*)d_in[11];
    const float* Wf       = (const float*)d_in[12];
    const float* bf       = (const float*)d_in[13];
    const float* Wsame    = (const float*)d_in[14];
    const float* Wdiff    = (const float*)d_in[15];
    const float* W1       = (const float*)d_in[16];
    const float* b1       = (const float*)d_in[17];
    const float* W2       = (const float*)d_in[18];
    const float* b2       = (const float*)d_in[19];
    const float* W3       = (const float*)d_in[20];
    const float* b3       = (const float*)d_in[21];
    const float* scale    = (const float*)d_in[22];

    float* out = (float*)d_out;

    float *elec1, *hmsg, *t1, *t2;
    cudaGetSymbolAddress((void**)&elec1, g_elec1);
    cudaGetSymbolAddress((void**)&hmsg,  g_hmsg);
    cudaGetSymbolAddress((void**)&t1,    g_t1);
    cudaGetSymbolAddress((void**)&t2,    g_t2);

    dim3 ggrid(DIM / 64, N_ELEC / 64);   // (4, 128) = 512 blocks
    dim3 gblk(128);

    gemm_silu<0><<<ggrid, gblk>>>(elec, W_in, b_in, nullptr, nullptr, nullptr, elec1);

    pair_kernel<<<N_ELEC / NPB, 256>>>(elec1, r, r_nb, s, s_nb, hinit_nb,
                                       ee_scales, ee_kernel, ee_bias, Wf, bf,
                                       Wsame, Wdiff, hmsg);

    gemm_silu<1><<<ggrid, gblk>>>(elec1, W1, b1, hmsg, nullptr, nullptr, t1);
    gemm_silu<1><<<ggrid, gblk>>>(t1, W2, b2, msg, nullptr, nullptr, t2);
    gemm_silu<2><<<ggrid, gblk>>>(t2, W3, b3, nullptr, elec1, scale, out);
}

// round 3
// speedup vs baseline: 1.4522x; 1.3434x over previous
#include <cuda_runtime.h>
#include <cuda_bf16.h>

constexpr int N_ELEC = 8192;
constexpr int DIM    = 256;
constexpr int NNB    = 24;
constexpr int F0     = 32;
constexpr int F1     = 16;
constexpr int NENV   = 8;
constexpr float CUTOFF = 5.0f;

__device__ float g_elec1[N_ELEC * DIM];
__device__ float g_hmsg [N_ELEC * DIM];
__device__ float g_t1   [N_ELEC * DIM];
__device__ float g_t2   [N_ELEC * DIM];

typedef unsigned long long u64;

__device__ __forceinline__ u64 pk2(float x, float y) {
    u64 r; asm("mov.b64 %0, {%1,%2};" : "=l"(r) : "f"(x), "f"(y)); return r;
}
__device__ __forceinline__ float2 upk2(u64 v) {
    float2 f; asm("mov.b64 {%0,%1}, %2;" : "=f"(f.x), "=f"(f.y) : "l"(v)); return f;
}
__device__ __forceinline__ u64 f2fma(u64 a, u64 b, u64 c) {
    u64 d; asm("fma.rn.f32x2 %0, %1, %2, %3;" : "=l"(d) : "l"(a), "l"(b), "l"(c));
    return d;
}

__device__ __forceinline__ float silu_f(float x) {
    float e = __expf(-x);
    return __fdividef(x, 1.0f + e);
}

// ---------------------------------------------------------------------------
// GEMM: out[8192,256] = epilogue(A[8192,256] @ W[256,256])
// BM=128, BN=64, BK=16, 128 threads, thread tile 8x8 (4 row-pairs x 8 cols),
// f32x2 packed FMA, B splat in registers.
// MODE 0: silu(acc+bias)   MODE 1: silu(acc+bias+extra)
// MODE 2: (silu(acc+bias)+res)*scale
// ---------------------------------------------------------------------------
template <int MODE>
__global__ __launch_bounds__(128) void gemm_silu(
    const float* __restrict__ A, const float* __restrict__ W,
    const float* __restrict__ bias, const float* __restrict__ extra,
    const float* __restrict__ res, const float* __restrict__ scale_p,
    float* __restrict__ out)
{
    __shared__ __align__(16) float As[16][128];   // [k][m]
    __shared__ __align__(16) float Bs[16][64];    // [k][n]

    const int tid = threadIdx.x;
    const int bm  = blockIdx.y;   // 64 tiles of 128 rows
    const int bn  = blockIdx.x;   // 4 tiles of 64 cols

    const int tx = tid & 7;       // n-group: cols tx*8 .. +7
    const int ty = tid >> 3;      // m-group: rows ty*8 .. +7 (0..15)

    // staging: A — one row per thread (row=tid), 16 k-floats per stage
    const float* Ag = A + (size_t)(bm * 128 + tid) * DIM;
    // staging: B — row tid>>3 (0..15), 8 cols at (tid&7)*8
    const float* Wg = W + (size_t)(tid >> 3) * DIM + bn * 64 + (tid & 7) * 8;

    u64 acc[4][8];
#pragma unroll
    for (int i = 0; i < 4; i++)
#pragma unroll
        for (int j = 0; j < 8; j++) acc[i][j] = 0ull;

    float4 pa[4];
    float4 pb[2];
    // prefetch stage 0
#pragma unroll
    for (int q = 0; q < 4; q++) pa[q] = *(const float4*)(Ag + q * 4);
    pb[0] = *(const float4*)(Wg);
    pb[1] = *(const float4*)(Wg + 4);

    for (int k0 = 0; k0 < DIM; k0 += 16) {
        // store staged regs to SMEM
        As[ 0][tid] = pa[0].x; As[ 1][tid] = pa[0].y; As[ 2][tid] = pa[0].z; As[ 3][tid] = pa[0].w;
        As[ 4][tid] = pa[1].x; As[ 5][tid] = pa[1].y; As[ 6][tid] = pa[1].z; As[ 7][tid] = pa[1].w;
        As[ 8][tid] = pa[2].x; As[ 9][tid] = pa[2].y; As[10][tid] = pa[2].z; As[11][tid] = pa[2].w;
        As[12][tid] = pa[3].x; As[13][tid] = pa[3].y; As[14][tid] = pa[3].z; As[15][tid] = pa[3].w;
        *(float4*)&Bs[tid >> 3][(tid & 7) * 8]     = pb[0];
        *(float4*)&Bs[tid >> 3][(tid & 7) * 8 + 4] = pb[1];
        __syncthreads();

        if (k0 + 16 < DIM) {
#pragma unroll
            for (int q = 0; q < 4; q++)
                pa[q] = *(const float4*)(Ag + k0 + 16 + q * 4);
            pb[0] = *(const float4*)(Wg + (size_t)(k0 + 16) * DIM);
            pb[1] = *(const float4*)(Wg + (size_t)(k0 + 16) * DIM + 4);
        }

#pragma unroll
        for (int kk = 0; kk < 16; kk++) {
            ulonglong2 av0 = *(const ulonglong2*)&As[kk][ty * 8];
            ulonglong2 av1 = *(const ulonglong2*)&As[kk][ty * 8 + 4];
            float4 bv0 = *(const float4*)&Bs[kk][tx * 8];
            float4 bv1 = *(const float4*)&Bs[kk][tx * 8 + 4];
            u64 a2[4] = { av0.x, av0.y, av1.x, av1.y };
            u64 b2[8] = { pk2(bv0.x, bv0.x), pk2(bv0.y, bv0.y),
                          pk2(bv0.z, bv0.z), pk2(bv0.w, bv0.w),
                          pk2(bv1.x, bv1.x), pk2(bv1.y, bv1.y),
                          pk2(bv1.z, bv1.z), pk2(bv1.w, bv1.w) };
#pragma unroll
            for (int i = 0; i < 4; i++)
#pragma unroll
                for (int j = 0; j < 8; j++)
                    acc[i][j] = f2fma(a2[i], b2[j], acc[i][j]);
        }
        __syncthreads();
    }

    // unpack: acc[i][j] -> rows (ty*8+2i, ty*8+2i+1), col tx*8+j
    float v[8][8];
#pragma unroll
    for (int i = 0; i < 4; i++)
#pragma unroll
        for (int j = 0; j < 8; j++) {
            float2 t = upk2(acc[i][j]);
            v[2 * i + 0][j] = t.x;
            v[2 * i + 1][j] = t.y;
        }

    const int col0 = bn * 64 + tx * 8;
    float sc = 1.0f;
    if (MODE == 2) sc = *scale_p;
    float4 bv0 = *(const float4*)(bias + col0);
    float4 bv1 = *(const float4*)(bias + col0 + 4);
    float bb[8] = { bv0.x, bv0.y, bv0.z, bv0.w, bv1.x, bv1.y, bv1.z, bv1.w };

#pragma unroll
    for (int rr = 0; rr < 8; rr++) {
        const int row = bm * 128 + ty * 8 + rr;
        const size_t off = (size_t)row * DIM + col0;
        float w[8];
#pragma unroll
        for (int j = 0; j < 8; j++) w[j] = v[rr][j] + bb[j];
        if (MODE == 1) {
            float4 e0 = *(const float4*)(extra + off);
            float4 e1 = *(const float4*)(extra + off + 4);
            w[0] += e0.x; w[1] += e0.y; w[2] += e0.z; w[3] += e0.w;
            w[4] += e1.x; w[5] += e1.y; w[6] += e1.z; w[7] += e1.w;
        }
        float o[8];
#pragma unroll
        for (int j = 0; j < 8; j++) o[j] = silu_f(w[j]);
        if (MODE == 2) {
            float4 r0 = *(const float4*)(res + off);
            float4 r1 = *(const float4*)(res + off + 4);
            o[0] = (o[0] + r0.x) * sc; o[1] = (o[1] + r0.y) * sc;
            o[2] = (o[2] + r0.z) * sc; o[3] = (o[3] + r0.w) * sc;
            o[4] = (o[4] + r1.x) * sc; o[5] = (o[5] + r1.y) * sc;
            o[6] = (o[6] + r1.z) * sc; o[7] = (o[7] + r1.w) * sc;
        }
        *(float4*)(out + off)     = make_float4(o[0], o[1], o[2], o[3]);
        *(float4*)(out + off + 4) = make_float4(o[4], o[5], o[6], o[7]);
    }
}

// ---------------------------------------------------------------------------
// Pair kernel: 8 electrons per block, 256 threads.
//  hmsg[n,d] = wd_d . (sum_k u_k beta_k) + (ws-wd)_d . (sum_k m_k u_k beta_k)
// W pair-vectors staged in SMEM (keeps registers ~60, no spills).
// ---------------------------------------------------------------------------
constexpr int NPB   = 8;
constexpr int PAIRS = NPB * NNB;   // 192

__global__ __launch_bounds__(256) void pair_kernel(
    const float* __restrict__ elec1,
    const float* __restrict__ r,
    const float* __restrict__ r_nb,
    const int*   __restrict__ s,
    const int*   __restrict__ s_nb,
    const float* __restrict__ hinit_nb,
    const float* __restrict__ ee_scales,
    const float* __restrict__ ee_kernel,
    const float* __restrict__ ee_bias,
    const float* __restrict__ Wf,
    const float* __restrict__ bf,
    const float* __restrict__ Wsame,
    const float* __restrict__ Wdiff,
    float* __restrict__ hinit_msg)
{
    __shared__ __align__(16) float beta_s[PAIRS][F1];   // 12 KB
    __shared__ float maskf_s[PAIRS];
    __shared__ u64  wd2_s [8][DIM];                     // 16 KB
    __shared__ u64  wsd2_s[8][DIM];                     // 16 KB
    __shared__ float eek_s[4 * F0];
    __shared__ float eeb_s[F0];
    __shared__ float wf_s[(F0 + NENV) * F1];
    __shared__ float bfv_s[F1];
    __shared__ float scl_s[NENV];

    const int tid = threadIdx.x;
    const int n0  = blockIdx.x * NPB;

    // stage params
    for (int i = tid; i < 4 * F0; i += 256) eek_s[i] = ee_kernel[i];
    for (int i = tid; i < F0; i += 256)     eeb_s[i] = ee_bias[i];
    for (int i = tid; i < (F0 + NENV) * F1; i += 256) wf_s[i] = Wf[i];
    if (tid < F1)   bfv_s[tid] = bf[tid];
    if (tid < NENV) scl_s[tid] = ee_scales[tid];

    // stage W pair-vectors (d = tid)
#pragma unroll
    for (int i = 0; i < 8; i++) {
        float d0 = Wdiff[(2 * i + 0) * DIM + tid];
        float d1 = Wdiff[(2 * i + 1) * DIM + tid];
        float s0 = Wsame[(2 * i + 0) * DIM + tid] - d0;
        float s1 = Wsame[(2 * i + 1) * DIM + tid] - d1;
        wd2_s [i][tid] = pk2(d0, d1);
        wsd2_s[i][tid] = pk2(s0, s1);
    }
    __syncthreads();

    // ---- Phase 1: per-pair beta (threads 0..191) ----
    if (tid < PAIRS) {
        const int nl = tid / NNB;
        const int k  = tid % NNB;
        const int n  = n0 + nl;

        const float rx = r[n * 3 + 0];
        const float ry = r[n * 3 + 1];
        const float rz = r[n * 3 + 2];
        const float* rn = r_nb + (size_t)(n * NNB + k) * 3;
        const float dx = rn[0] - rx;
        const float dy = rn[1] - ry;
        const float dz = rn[2] - rz;
        const float dist = sqrtf(dx * dx + dy * dy + dz * dz + 1e-12f);

        float feats[4] = { dist, dx, dy, dz };
        float h[F0];
#pragma unroll
        for (int j = 0; j < F0; j++) {
            float t = eeb_s[j];
#pragma unroll
            for (int f = 0; f < 4; f++) t += feats[f] * eek_s[f * F0 + j];
            h[j] = silu_f(t);
        }
        float env[NENV];
#pragma unroll
        for (int e = 0; e < NENV; e++) {
            float q = __fdividef(dist, scl_s[e]);
            env[e] = __expf(-q * q);
        }
        const float xx  = dist * (1.0f / CUTOFF);
        const float cut = (dist < CUTOFF)
                        ? (1.0f - xx) * (1.0f - xx) * (1.0f + 2.0f * xx)
                        : 0.0f;
#pragma unroll
        for (int i = 0; i < F1; i++) {
            float b = bfv_s[i];
#pragma unroll
            for (int j = 0; j < F0; j++)   b += h[j]   * wf_s[j * F1 + i];
#pragma unroll
            for (int e = 0; e < NENV; e++) b += env[e] * wf_s[(F0 + e) * F1 + i];
            beta_s[tid][i] = b * cut;
        }
        maskf_s[tid] = (s[n] == s_nb[n * NNB + k]) ? 1.0f : 0.0f;
    }
    __syncthreads();

    // ---- Phase 2: per-channel reduction (thread d = 0..255) ----
    const int d = tid;

    for (int nl = 0; nl < NPB; nl++) {
        const int n = n0 + nl;
        const float e1 = elec1[(size_t)n * DIM + d];
        const float* hb = hinit_nb + ((size_t)n * NNB) * DIM + d;

        u64 vall[8], vsm[8];
#pragma unroll
        for (int i = 0; i < 8; i++) { vall[i] = 0ull; vsm[i] = 0ull; }

#pragma unroll
        for (int h = 0; h < 3; h++) {
            float uu[8];
#pragma unroll
            for (int kk = 0; kk < 8; kk++)
                uu[kk] = e1 + hb[(size_t)(h * 8 + kk) * DIM];
#pragma unroll
            for (int kk = 0; kk < 8; kk++) {
                const int pair = nl * NNB + h * 8 + kk;
                const float u  = silu_f(uu[kk]);
                const float um = u * maskf_s[pair];
                const u64 u2   = pk2(u, u);
                const u64 um2  = pk2(um, um);
                const u64* bp  = (const u64*)beta_s[pair];
#pragma unroll
                for (int i = 0; i < 8; i++) {
                    vall[i] = f2fma(u2,  bp[i], vall[i]);
                    vsm[i]  = f2fma(um2, bp[i], vsm[i]);
                }
            }
        }

        u64 r2 = 0ull;
#pragma unroll
        for (int i = 0; i < 8; i++) r2 = f2fma(wd2_s[i][d],  vall[i], r2);
#pragma unroll
        for (int i = 0; i < 8; i++) r2 = f2fma(wsd2_s[i][d], vsm[i],  r2);
        float2 rr = upk2(r2);
        hinit_msg[(size_t)n * DIM + d] = rr.x + rr.y;
    }
}

// ---------------------------------------------------------------------------
extern "C" void kernel_launch(void* const* d_in, const int* in_sizes, int n_in,
                              void* d_out, int out_size)
{
    const float* elec     = (const float*)d_in[0];
    const float* msg      = (const float*)d_in[1];
    const float* r        = (const float*)d_in[2];
    const float* r_nb     = (const float*)d_in[3];
    const int*   s        = (const int*)  d_in[4];
    const int*   s_nb     = (const int*)  d_in[5];
    const float* hinit_nb = (const float*)d_in[6];
    const float* W_in     = (const float*)d_in[7];
    const float* b_in     = (const float*)d_in[8];
    const float* ee_scales= (const float*)d_in[9];
    const float* ee_kernel= (const float*)d_in[10];
    const float* ee_bias  = (const float*)d_in[11];
    const float* Wf       = (const float*)d_in[12];
    const float* bf       = (const float*)d_in[13];
    const float* Wsame    = (const float*)d_in[14];
    const float* Wdiff    = (const float*)d_in[15];
    const float* W1       = (const float*)d_in[16];
    const float* b1       = (const float*)d_in[17];
    const float* W2       = (const float*)d_in[18];
    const float* b2       = (const float*)d_in[19];
    const float* W3       = (const float*)d_in[20];
    const float* b3       = (const float*)d_in[21];
    const float* scale    = (const float*)d_in[22];

    float* out = (float*)d_out;

    float *elec1, *hmsg, *t1, *t2;
    cudaGetSymbolAddress((void**)&elec1, g_elec1);
    cudaGetSymbolAddress((void**)&hmsg,  g_hmsg);
    cudaGetSymbolAddress((void**)&t1,    g_t1);
    cudaGetSymbolAddress((void**)&t2,    g_t2);

    dim3 ggrid(DIM / 64, N_ELEC / 128);   // (4, 64) = 256 blocks
    dim3 gblk(128);

    gemm_silu<0><<<ggrid, gblk>>>(elec, W_in, b_in, nullptr, nullptr, nullptr, elec1);

    pair_kernel<<<N_ELEC / NPB, 256>>>(elec1, r, r_nb, s, s_nb, hinit_nb,
                                       ee_scales, ee_kernel, ee_bias, Wf, bf,
                                       Wsame, Wdiff, hmsg);

    gemm_silu<1><<<ggrid, gblk>>>(elec1, W1, b1, hmsg, nullptr, nullptr, t1);
    gemm_silu<1><<<ggrid, gblk>>>(t1, W2, b2, msg, nullptr, nullptr, t2);
    gemm_silu<2><<<ggrid, gblk>>>(t2, W3, b3, nullptr, elec1, scale, out);
}

// round 4
// speedup vs baseline: 1.6529x; 1.1382x over previous
#include <cuda_runtime.h>
#include <cuda_bf16.h>

constexpr int N_ELEC = 8192;
constexpr int DIM    = 256;
constexpr int NNB    = 24;
constexpr int F0     = 32;
constexpr int F1     = 16;
constexpr int NENV   = 8;
constexpr float CUTOFF = 5.0f;

__device__ float g_elec1[N_ELEC * DIM];
__device__ float g_hmsg [N_ELEC * DIM];
__device__ float g_t1   [N_ELEC * DIM];
__device__ float g_t2   [N_ELEC * DIM];

typedef unsigned long long u64;

__device__ __forceinline__ u64 pk2(float x, float y) {
    u64 r; asm("mov.b64 %0, {%1,%2};" : "=l"(r) : "f"(x), "f"(y)); return r;
}
__device__ __forceinline__ float2 upk2(u64 v) {
    float2 f; asm("mov.b64 {%0,%1}, %2;" : "=f"(f.x), "=f"(f.y) : "l"(v)); return f;
}
__device__ __forceinline__ u64 f2fma(u64 a, u64 b, u64 c) {
    u64 d; asm("fma.rn.f32x2 %0, %1, %2, %3;" : "=l"(d) : "l"(a), "l"(b), "l"(c));
    return d;
}

__device__ __forceinline__ float silu_f(float x) {
    float e = __expf(-x);
    return __fdividef(x, 1.0f + e);
}

// ---------------------------------------------------------------------------
// GEMM: out[8192,256] = epilogue(A[8192,256] @ W[256,256])
// BM=64, BN=64, BK=16, 128 threads, thread tile 8x4 (4 row-pairs x 4 cols),
// f32x2 FMA, double-buffered SMEM (1 sync per k-stage), grid 512 blocks.
// MODE 0: silu(acc+bias)   MODE 1: silu(acc+bias+extra)
// MODE 2: (silu(acc+bias)+res)*scale
// ---------------------------------------------------------------------------
template <int MODE>
__global__ __launch_bounds__(128) void gemm_silu(
    const float* __restrict__ A, const float* __restrict__ W,
    const float* __restrict__ bias, const float* __restrict__ extra,
    const float* __restrict__ res, const float* __restrict__ scale_p,
    float* __restrict__ out)
{
    __shared__ __align__(16) float As[2][16][64];   // [buf][k][m]
    __shared__ __align__(16) float Bs[2][16][64];   // [buf][k][n]

    const int tid = threadIdx.x;
    const int bm  = blockIdx.y;   // 128 tiles of 64 rows
    const int bn  = blockIdx.x;   // 4 tiles of 64 cols

    const int tx = tid & 15;      // col group: cols tx*4 .. +3
    const int ty = tid >> 4;      // row group: rows ty*8 .. +7

    const int arow = tid >> 1;          // 0..63
    const int acol = (tid & 1) * 8;     // 0 or 8
    const int brow = tid >> 3;          // 0..15
    const int bcol = (tid & 7) * 8;     // 0..56

    const float* Ag = A + (size_t)(bm * 64 + arow) * DIM + acol;
    const float* Wg = W + (size_t)brow * DIM + bn * 64 + bcol;

    u64 acc[4][4];
#pragma unroll
    for (int i = 0; i < 4; i++)
#pragma unroll
        for (int j = 0; j < 4; j++) acc[i][j] = 0ull;

    float4 pa0, pa1, pb0, pb1;
    pa0 = *(const float4*)(Ag);
    pa1 = *(const float4*)(Ag + 4);
    pb0 = *(const float4*)(Wg);
    pb1 = *(const float4*)(Wg + 4);

    // store stage 0
    {
        float a[8] = { pa0.x, pa0.y, pa0.z, pa0.w, pa1.x, pa1.y, pa1.z, pa1.w };
#pragma unroll
        for (int j = 0; j < 8; j++) As[0][acol + j][arow] = a[j];
        *(float4*)&Bs[0][brow][bcol]     = pb0;
        *(float4*)&Bs[0][brow][bcol + 4] = pb1;
    }
    __syncthreads();

    int buf = 0;
    for (int k0 = 0; k0 < DIM; k0 += 16) {
        const bool more = (k0 + 16 < DIM);
        if (more) {
            pa0 = *(const float4*)(Ag + k0 + 16);
            pa1 = *(const float4*)(Ag + k0 + 16 + 4);
            pb0 = *(const float4*)(Wg + (size_t)(k0 + 16) * DIM);
            pb1 = *(const float4*)(Wg + (size_t)(k0 + 16) * DIM + 4);
        }

#pragma unroll
        for (int kk = 0; kk < 16; kk++) {
            ulonglong2 av0 = *(const ulonglong2*)&As[buf][kk][ty * 8];
            ulonglong2 av1 = *(const ulonglong2*)&As[buf][kk][ty * 8 + 4];
            float4 bv = *(const float4*)&Bs[buf][kk][tx * 4];
            u64 a2[4] = { av0.x, av0.y, av1.x, av1.y };
            u64 b2[4] = { pk2(bv.x, bv.x), pk2(bv.y, bv.y),
                          pk2(bv.z, bv.z), pk2(bv.w, bv.w) };
#pragma unroll
            for (int i = 0; i < 4; i++)
#pragma unroll
                for (int j = 0; j < 4; j++)
                    acc[i][j] = f2fma(a2[i], b2[j], acc[i][j]);
        }

        if (more) {
            float a[8] = { pa0.x, pa0.y, pa0.z, pa0.w, pa1.x, pa1.y, pa1.z, pa1.w };
#pragma unroll
            for (int j = 0; j < 8; j++) As[buf ^ 1][acol + j][arow] = a[j];
            *(float4*)&Bs[buf ^ 1][brow][bcol]     = pb0;
            *(float4*)&Bs[buf ^ 1][brow][bcol + 4] = pb1;
        }
        __syncthreads();
        buf ^= 1;
    }

    // unpack accumulators: acc[i][j] -> rows (ty*8+2i, +1), col tx*4+j
    float v[8][4];
#pragma unroll
    for (int i = 0; i < 4; i++)
#pragma unroll
        for (int j = 0; j < 4; j++) {
            float2 t = upk2(acc[i][j]);
            v[2 * i + 0][j] = t.x;
            v[2 * i + 1][j] = t.y;
        }

    const int col0 = bn * 64 + tx * 4;
    float sc = 1.0f;
    if (MODE == 2) sc = *scale_p;
    float4 bv = *(const float4*)(bias + col0);
    float bb[4] = { bv.x, bv.y, bv.z, bv.w };

#pragma unroll
    for (int rr = 0; rr < 8; rr++) {
        const int row = bm * 64 + ty * 8 + rr;
        const size_t off = (size_t)row * DIM + col0;
        float w[4];
#pragma unroll
        for (int j = 0; j < 4; j++) w[j] = v[rr][j] + bb[j];
        if (MODE == 1) {
            float4 e = *(const float4*)(extra + off);
            w[0] += e.x; w[1] += e.y; w[2] += e.z; w[3] += e.w;
        }
        float o[4];
#pragma unroll
        for (int j = 0; j < 4; j++) o[j] = silu_f(w[j]);
        if (MODE == 2) {
            float4 rv = *(const float4*)(res + off);
            o[0] = (o[0] + rv.x) * sc; o[1] = (o[1] + rv.y) * sc;
            o[2] = (o[2] + rv.z) * sc; o[3] = (o[3] + rv.w) * sc;
        }
        *(float4*)(out + off) = make_float4(o[0], o[1], o[2], o[3]);
    }
}

// ---------------------------------------------------------------------------
// Pair kernel: 8 electrons per block, 256 threads.
//  hmsg[n,d] = wd_d . (sum_k u_k beta_k) + (ws-wd)_d . (sum_k m_k u_k beta_k)
// ---------------------------------------------------------------------------
constexpr int NPB   = 8;
constexpr int PAIRS = NPB * NNB;   // 192

__global__ __launch_bounds__(256) void pair_kernel(
    const float* __restrict__ elec1,
    const float* __restrict__ r,
    const float* __restrict__ r_nb,
    const int*   __restrict__ s,
    const int*   __restrict__ s_nb,
    const float* __restrict__ hinit_nb,
    const float* __restrict__ ee_scales,
    const float* __restrict__ ee_kernel,
    const float* __restrict__ ee_bias,
    const float* __restrict__ Wf,
    const float* __restrict__ bf,
    const float* __restrict__ Wsame,
    const float* __restrict__ Wdiff,
    float* __restrict__ hinit_msg)
{
    __shared__ __align__(16) float beta_s[PAIRS][F1];   // 12 KB
    __shared__ float maskf_s[PAIRS];
    __shared__ u64  wd2_s [8][DIM];                     // 16 KB
    __shared__ u64  wsd2_s[8][DIM];                     // 16 KB
    __shared__ float eek_s[4 * F0];
    __shared__ float eeb_s[F0];
    __shared__ float wf_s[(F0 + NENV) * F1];
    __shared__ float bfv_s[F1];
    __shared__ float scl_s[NENV];

    const int tid = threadIdx.x;
    const int n0  = blockIdx.x * NPB;

    for (int i = tid; i < 4 * F0; i += 256) eek_s[i] = ee_kernel[i];
    for (int i = tid; i < F0; i += 256)     eeb_s[i] = ee_bias[i];
    for (int i = tid; i < (F0 + NENV) * F1; i += 256) wf_s[i] = Wf[i];
    if (tid < F1)   bfv_s[tid] = bf[tid];
    if (tid < NENV) scl_s[tid] = ee_scales[tid];

#pragma unroll
    for (int i = 0; i < 8; i++) {
        float d0 = Wdiff[(2 * i + 0) * DIM + tid];
        float d1 = Wdiff[(2 * i + 1) * DIM + tid];
        float s0 = Wsame[(2 * i + 0) * DIM + tid] - d0;
        float s1 = Wsame[(2 * i + 1) * DIM + tid] - d1;
        wd2_s [i][tid] = pk2(d0, d1);
        wsd2_s[i][tid] = pk2(s0, s1);
    }
    __syncthreads();

    // ---- Phase 1: per-pair beta (threads 0..191) ----
    if (tid < PAIRS) {
        const int nl = tid / NNB;
        const int k  = tid % NNB;
        const int n  = n0 + nl;

        const float rx = r[n * 3 + 0];
        const float ry = r[n * 3 + 1];
        const float rz = r[n * 3 + 2];
        const float* rn = r_nb + (size_t)(n * NNB + k) * 3;
        const float dx = rn[0] - rx;
        const float dy = rn[1] - ry;
        const float dz = rn[2] - rz;
        const float dist = sqrtf(dx * dx + dy * dy + dz * dz + 1e-12f);

        float feats[4] = { dist, dx, dy, dz };
        float h[F0];
#pragma unroll
        for (int j = 0; j < F0; j++) {
            float t = eeb_s[j];
#pragma unroll
            for (int f = 0; f < 4; f++) t += feats[f] * eek_s[f * F0 + j];
            h[j] = silu_f(t);
        }
        float env[NENV];
#pragma unroll
        for (int e = 0; e < NENV; e++) {
            float q = __fdividef(dist, scl_s[e]);
            env[e] = __expf(-q * q);
        }
        const float xx  = dist * (1.0f / CUTOFF);
        const float cut = (dist < CUTOFF)
                        ? (1.0f - xx) * (1.0f - xx) * (1.0f + 2.0f * xx)
                        : 0.0f;
#pragma unroll
        for (int i = 0; i < F1; i++) {
            float b = bfv_s[i];
#pragma unroll
            for (int j = 0; j < F0; j++)   b += h[j]   * wf_s[j * F1 + i];
#pragma unroll
            for (int e = 0; e < NENV; e++) b += env[e] * wf_s[(F0 + e) * F1 + i];
            beta_s[tid][i] = b * cut;
        }
        maskf_s[tid] = (s[n] == s_nb[n * NNB + k]) ? 1.0f : 0.0f;
    }
    __syncthreads();

    // ---- Phase 2: per-channel reduction (thread d = 0..255) ----
    const int d = tid;

    for (int nl = 0; nl < NPB; nl++) {
        const int n = n0 + nl;
        const float e1 = elec1[(size_t)n * DIM + d];
        const float* hb = hinit_nb + ((size_t)n * NNB) * DIM + d;

        // batch all 24 neighbor loads (MLP) then silu
        float uu[NNB];
#pragma unroll
        for (int k = 0; k < NNB; k++) uu[k] = e1 + hb[(size_t)k * DIM];
#pragma unroll
        for (int k = 0; k < NNB; k++) uu[k] = silu_f(uu[k]);

        u64 vall[8], vsm[8];
#pragma unroll
        for (int i = 0; i < 8; i++) { vall[i] = 0ull; vsm[i] = 0ull; }

#pragma unroll
        for (int k = 0; k < NNB; k++) {
            const int pair = nl * NNB + k;
            const float u  = uu[k];
            const float um = u * maskf_s[pair];
            const u64 u2   = pk2(u, u);
            const u64 um2  = pk2(um, um);
            const u64* bp  = (const u64*)beta_s[pair];
#pragma unroll
            for (int i = 0; i < 8; i++) {
                vall[i] = f2fma(u2,  bp[i], vall[i]);
                vsm[i]  = f2fma(um2, bp[i], vsm[i]);
            }
        }

        u64 r2 = 0ull;
#pragma unroll
        for (int i = 0; i < 8; i++) r2 = f2fma(wd2_s[i][d],  vall[i], r2);
#pragma unroll
        for (int i = 0; i < 8; i++) r2 = f2fma(wsd2_s[i][d], vsm[i],  r2);
        float2 rr = upk2(r2);
        hinit_msg[(size_t)n * DIM + d] = rr.x + rr.y;
    }
}

// ---------------------------------------------------------------------------
extern "C" void kernel_launch(void* const* d_in, const int* in_sizes, int n_in,
                              void* d_out, int out_size)
{
    const float* elec     = (const float*)d_in[0];
    const float* msg      = (const float*)d_in[1];
    const float* r        = (const float*)d_in[2];
    const float* r_nb     = (const float*)d_in[3];
    const int*   s        = (const int*)  d_in[4];
    const int*   s_nb     = (const int*)  d_in[5];
    const float* hinit_nb = (const float*)d_in[6];
    const float* W_in     = (const float*)d_in[7];
    const float* b_in     = (const float*)d_in[8];
    const float* ee_scales= (const float*)d_in[9];
    const float* ee_kernel= (const float*)d_in[10];
    const float* ee_bias  = (const float*)d_in[11];
    const float* Wf       = (const float*)d_in[12];
    const float* bf       = (const float*)d_in[13];
    const float* Wsame    = (const float*)d_in[14];
    const float* Wdiff    = (const float*)d_in[15];
    const float* W1       = (const float*)d_in[16];
    const float* b1       = (const float*)d_in[17];
    const float* W2       = (const float*)d_in[18];
    const float* b2       = (const float*)d_in[19];
    const float* W3       = (const float*)d_in[20];
    const float* b3       = (const float*)d_in[21];
    const float* scale    = (const float*)d_in[22];

    float* out = (float*)d_out;

    float *elec1, *hmsg, *t1, *t2;
    cudaGetSymbolAddress((void**)&elec1, g_elec1);
    cudaGetSymbolAddress((void**)&hmsg,  g_hmsg);
    cudaGetSymbolAddress((void**)&t1,    g_t1);
    cudaGetSymbolAddress((void**)&t2,    g_t2);

    dim3 ggrid(DIM / 64, N_ELEC / 64);   // (4, 128) = 512 blocks
    dim3 gblk(128);

    gemm_silu<0><<<ggrid, gblk>>>(elec, W_in, b_in, nullptr, nullptr, nullptr, elec1);

    pair_kernel<<<N_ELEC / NPB, 256>>>(elec1, r, r_nb, s, s_nb, hinit_nb,
                                       ee_scales, ee_kernel, ee_bias, Wf, bf,
                                       Wsame, Wdiff, hmsg);

    gemm_silu<1><<<ggrid, gblk>>>(elec1, W1, b1, hmsg, nullptr, nullptr, t1);
    gemm_silu<1><<<ggrid, gblk>>>(t1, W2, b2, msg, nullptr, nullptr, t2);
    gemm_silu<2><<<ggrid, gblk>>>(t2, W3, b3, nullptr, elec1, scale, out);
}